// round 7
// baseline (speedup 1.0000x reference)
#include <cuda_runtime.h>
#include <math.h>

#define RPB  8
#define NT   512
#define PL   132
#define ROWF 1188          /* 9 planes * 132 */
#define RS_MUL 0.08838834764831845f

__device__ float g_coef[11 * 125];

/* ---------------- W3J init (fp64, replicates reference) ---------------- */
__device__ double dfact(int n) { double r = 1; for (int i = 2; i <= n; i++) r *= i; return r; }

__device__ double cg_d(int j1, int m1, int j2, int m2, int j3, int m3) {
    if (m1 + m2 != m3) return 0.0;
    double pre = sqrt((2.0 * j3 + 1.0) * dfact(j3 + j1 - j2) * dfact(j3 - j1 + j2) *
                      dfact(j1 + j2 - j3) / dfact(j1 + j2 + j3 + 1));
    pre *= sqrt(dfact(j3 + m3) * dfact(j3 - m3) * dfact(j1 - m1) * dfact(j1 + m1) *
                dfact(j2 - m2) * dfact(j2 + m2));
    double s = 0;
    for (int k = 0; k <= j1 + j2 - j3; k++) {
        int d0 = k, d1 = j1 + j2 - j3 - k, d2 = j1 - m1 - k;
        int d3 = j2 + m2 - k, d4 = j3 - j2 + m1 + k, d5 = j3 - j1 - m2 + k;
        if (d0 < 0 || d1 < 0 || d2 < 0 || d3 < 0 || d4 < 0 || d5 < 0) continue;
        double den = dfact(d0) * dfact(d1) * dfact(d2) * dfact(d3) * dfact(d4) * dfact(d5);
        s += ((k & 1) ? -1.0 : 1.0) / den;
    }
    return pre * s;
}

__global__ void w3j_init() {
    __shared__ double Wc[125], Wr[125];
    __shared__ double Qr[3][25], Qi[3][25];
    __shared__ double s_sign;
    const int L1[11] = {0,0,0,1,1,1,1,2,2,2,2};
    const int L2[11] = {0,1,2,0,1,1,2,0,1,2,2};
    const int L3[11] = {0,1,2,1,0,2,1,2,1,0,2};
    const int NP[3] = {3, 4, 4};
    int ins = blockIdx.x;
    int l1 = L1[ins], l2 = L2[ins], l3 = L3[ins];
    int d1 = 2*l1+1, d2 = 2*l2+1, d3 = 2*l3+1;
    int t = threadIdx.x;
    int x = t / 25, y = (t / 5) % 5, z = t % 5;

    if (t == 0) {
        int ls[3] = {l1, l2, l3};
        for (int q = 0; q < 3; q++) {
            int l = ls[q];
            for (int a = 0; a < 25; a++) { Qr[q][a] = 0; Qi[q][a] = 0; }
            Qr[q][l*5 + l] = 1.0;
            double s = 1.0 / sqrt(2.0);
            for (int m = 1; m <= l; m++) {
                double sg = (m & 1) ? -1.0 : 1.0;
                Qr[q][(l+m)*5 + (l-m)] = s;
                Qr[q][(l+m)*5 + (l+m)] = sg * s;
                Qi[q][(l-m)*5 + (l-m)] = s;
                Qi[q][(l-m)*5 + (l+m)] = -sg * s;
            }
        }
    }
    double wc = 0;
    if (x < d1 && y < d2 && z < d3) {
        int m1 = x - l1, m2 = y - l2, m3 = z - l3;
        if (m3 == -(m1 + m2)) {
            int e = l1 - l2 - m3;
            double sg = (e & 1) ? -1.0 : 1.0;
            wc = sg / sqrt(2.0 * l3 + 1.0) * cg_d(l1, m1, l2, m2, l3, -m3);
        }
    }
    Wc[t] = wc;
    __syncthreads();

    double acc = 0;
    if (x < d1 && y < d2 && z < d3) {
        for (int a = 0; a < d1; a++)
            for (int b = 0; b < d2; b++) {
                double q1r = Qr[0][x*5+a], q1i = Qi[0][x*5+a];
                double q2r = Qr[1][y*5+b], q2i = Qi[1][y*5+b];
                double ur = q1r * q2r - q1i * q2i;
                double ui = q1r * q2i + q1i * q2r;
                for (int c = 0; c < d3; c++) {
                    double w = Wc[a*25 + b*5 + c];
                    if (w != 0.0) {
                        double re = ur * Qr[2][z*5+c] - ui * Qi[2][z*5+c];
                        acc += re * w;
                    }
                }
            }
    }
    Wr[t] = acc;
    __syncthreads();

    if (t == 0) {
        double amax = 0;
        for (int a = 0; a < d1; a++) for (int b = 0; b < d2; b++) for (int c = 0; c < d3; c++) {
            double av = fabs(Wr[a*25 + b*5 + c]);
            if (av > amax) amax = av;
        }
        double sg = 1.0; int done = 0;
        for (int a = 0; a < d1; a++) for (int b = 0; b < d2; b++) for (int c = 0; c < d3; c++) {
            double w = Wr[a*25 + b*5 + c];
            if (!done && fabs(w) >= amax * (1.0 - 1e-9)) { sg = (w >= 0) ? 1.0 : -1.0; done = 1; }
        }
        /* (2,2,2): mixed-sign max tie resolved by numpy argmax to a negative
           element (verified empirically in R5->R6). */
        if (ins == 10) sg = -sg;
        s_sign = sg;
    }
    __syncthreads();

    double pw = sqrt((2.0 * l3 + 1.0) / (double)NP[l3]);
    float o = 0.f;
    if (x < d1 && y < d2 && z < d3) o = (float)(Wr[t] * s_sign * pw);
    g_coef[ins * 125 + t] = o;
}

/* ---------------- Main fused kernel ---------------- */
__device__ __forceinline__ void stage_w(const float* __restrict__ gw, float* wt, int t) {
#pragma unroll
    for (int it = 0; it < 8; ++it) {
        int flat = it * NT + t;           /* 4096 float4 = 128x128 */
        int u = flat >> 5;
        int v4 = (flat & 31) << 2;
        float4 g = *(const float4*)(gw + u * 128 + v4);
        wt[(v4 + 0) * PL + u] = g.x;
        wt[(v4 + 1) * PL + u] = g.y;
        wt[(v4 + 2) * PL + u] = g.z;
        wt[(v4 + 3) * PL + u] = g.w;
    }
}

template <int DIM>
__device__ __forceinline__ void gemm_l(const float* __restrict__ inb, float* __restrict__ outb,
                                       const float* __restrict__ wt,
                                       const float* __restrict__ bias,
                                       int v, int g, int loff) {
    float acc[2][DIM];
#pragma unroll
    for (int r = 0; r < 2; r++)
#pragma unroll
        for (int i = 0; i < DIM; i++) acc[r][i] = 0.f;

    const float* a0 = inb + g * 2 * ROWF + loff;
    const float* wv = wt + v * PL;
#pragma unroll
    for (int u = 0; u < 128; u += 4) {
        float4 w = *(const float4*)(wv + u);
#pragma unroll
        for (int r = 0; r < 2; r++)
#pragma unroll
            for (int i = 0; i < DIM; i++) {
                float4 a = *(const float4*)(a0 + r * ROWF + i * PL + u);
                acc[r][i] = fmaf(a.x, w.x, acc[r][i]);
                acc[r][i] = fmaf(a.y, w.y, acc[r][i]);
                acc[r][i] = fmaf(a.z, w.z, acc[r][i]);
                acc[r][i] = fmaf(a.w, w.w, acc[r][i]);
            }
    }
    float bv = bias ? bias[v] : 0.f;
#pragma unroll
    for (int r = 0; r < 2; r++)
#pragma unroll
        for (int i = 0; i < DIM; i++)
            outb[(g * 2 + r) * ROWF + loff + i * PL + v] = acc[r][i] * RS_MUL + bv;
}

#define TP_INS(n, D1, D2, D3, B1, B2, B3)                                   \
    do {                                                                    \
        float w_ = TW[(n)*128 + u];                                         \
        _Pragma("unroll") for (int xx = 0; xx < (D1); xx++)                 \
        _Pragma("unroll") for (int yy = 0; yy < (D2); yy++) {               \
            float t2 = w_ * cl[(B1) + xx] * cr[(B2) + yy];                  \
            _Pragma("unroll") for (int zz = 0; zz < (D3); zz++)             \
                o[(B3) + zz] = fmaf(t2, CF[(n)*125 + xx*25 + yy*5 + zz],    \
                                    o[(B3) + zz]);                          \
        }                                                                   \
    } while (0)

__global__ void __launch_bounds__(NT, 1)
self_layer_kernel(const float* __restrict__ x, const float* __restrict__ oldf,
                  const float* __restrict__ wl, const float* __restrict__ bl,
                  const float* __restrict__ wr, const float* __restrict__ br,
                  const float* __restrict__ wp, const float* __restrict__ bp,
                  const float* __restrict__ tpw, const float* __restrict__ lnw,
                  const float* __restrict__ lnb, float* __restrict__ out, int N) {
    extern __shared__ float sm[];
    float* A  = sm;                  /* 8*1188 */
    float* Bf = A + RPB * ROWF;
    float* Cf = Bf + RPB * ROWF;
    float* WT = Cf + RPB * ROWF;     /* 128*132 */
    float* CF = WT + 128 * PL;       /* 1375 */
    float* TW = CF + 1375;           /* 1408 */
    float* RS = TW + 1408;           /* 32 */

    int t = threadIdx.x;
    int n0 = blockIdx.x * RPB;

    /* load x -> planar A */
    for (int idx = t; idx < RPB * 1152; idx += NT) {
        int r = idx / 1152, jj = idx - r * 1152;
        int n = n0 + r;
        float val = (n < N) ? x[(size_t)n * 1152 + jj] : 0.f;
        int p, u;
        if (jj < 128)      { p = 0; u = jj; }
        else if (jj < 512) { int q = jj - 128; u = q / 3; p = 1 + (q - u * 3); }
        else               { int q = jj - 512; u = q / 5; p = 4 + (q - u * 5); }
        A[r * ROWF + p * PL + u] = val;
    }
    for (int i = t; i < 1375; i += NT) CF[i] = g_coef[i];
    for (int i = t; i < 1408; i += NT) TW[i] = tpw[i];
    __syncthreads();

    int v = t & 127, g = t >> 7;     /* g in 0..3, 2 rows each */

    /* lin_l : A -> Bf */
    stage_w(wl,         WT, t); __syncthreads(); gemm_l<1>(A, Bf, WT, bl, v, g, 0);      __syncthreads();
    stage_w(wl + 16384, WT, t); __syncthreads(); gemm_l<3>(A, Bf, WT, 0,  v, g, PL);     __syncthreads();
    stage_w(wl + 32768, WT, t); __syncthreads(); gemm_l<5>(A, Bf, WT, 0,  v, g, 4 * PL); __syncthreads();
    /* lin_r : A -> Cf */
    stage_w(wr,         WT, t); __syncthreads(); gemm_l<1>(A, Cf, WT, br, v, g, 0);      __syncthreads();
    stage_w(wr + 16384, WT, t); __syncthreads(); gemm_l<3>(A, Cf, WT, 0,  v, g, PL);     __syncthreads();
    stage_w(wr + 32768, WT, t); __syncthreads(); gemm_l<5>(A, Cf, WT, 0,  v, g, 4 * PL); __syncthreads();

    /* tensor product: Bf,Cf -> A  (RPB*128 = 1024 items, 2 passes) */
#pragma unroll 1
    for (int it = 0; it < 2; ++it) {
        int idx = it * NT + t;
        int r = idx >> 7, u = idx & 127;
        int base = r * ROWF + u;
        float cl[9], cr[9], o[9];
#pragma unroll
        for (int c = 0; c < 9; c++) { cl[c] = Bf[base + c * PL]; cr[c] = Cf[base + c * PL]; o[c] = 0.f; }
        TP_INS(0, 1, 1, 1, 0, 0, 0);
        TP_INS(1, 1, 3, 3, 0, 1, 1);
        TP_INS(2, 1, 5, 5, 0, 4, 4);
        TP_INS(3, 3, 1, 3, 1, 0, 1);
        TP_INS(4, 3, 3, 1, 1, 1, 0);
        TP_INS(5, 3, 3, 5, 1, 1, 4);
        TP_INS(6, 3, 5, 3, 1, 4, 1);
        TP_INS(7, 5, 1, 5, 4, 0, 4);
        TP_INS(8, 5, 3, 3, 4, 1, 1);
        TP_INS(9, 5, 5, 1, 4, 4, 0);
        TP_INS(10, 5, 5, 5, 4, 4, 4);
#pragma unroll
        for (int c = 0; c < 9; c++) A[base + c * PL] = o[c];
    }
    __syncthreads();

    /* lin_p : A -> Bf */
    stage_w(wp,         WT, t); __syncthreads(); gemm_l<1>(A, Bf, WT, bp, v, g, 0);      __syncthreads();
    stage_w(wp + 16384, WT, t); __syncthreads(); gemm_l<3>(A, Bf, WT, 0,  v, g, PL);     __syncthreads();
    stage_w(wp + 32768, WT, t); __syncthreads(); gemm_l<5>(A, Bf, WT, 0,  v, g, 4 * PL); __syncthreads();

    /* e3norm stats: one warp per row */
    int wid = t >> 5, lane = t & 31;
    if (wid < RPB) {
        int r = wid;
        const float* fr = Bf + r * ROWF;
        float s0 = 0, q0 = 0, q1 = 0, q2 = 0;
        {
            float4 a = *(const float4*)(fr + lane * 4);
            s0 = a.x + a.y + a.z + a.w;
            q0 = a.x * a.x + a.y * a.y + a.z * a.z + a.w * a.w;
        }
#pragma unroll
        for (int p = 1; p < 4; p++) {
            float4 a = *(const float4*)(fr + p * PL + lane * 4);
            q1 += a.x * a.x + a.y * a.y + a.z * a.z + a.w * a.w;
        }
#pragma unroll
        for (int p = 4; p < 9; p++) {
            float4 a = *(const float4*)(fr + p * PL + lane * 4);
            q2 += a.x * a.x + a.y * a.y + a.z * a.z + a.w * a.w;
        }
#pragma unroll
        for (int off = 16; off; off >>= 1) {
            s0 += __shfl_xor_sync(0xffffffffu, s0, off);
            q0 += __shfl_xor_sync(0xffffffffu, q0, off);
            q1 += __shfl_xor_sync(0xffffffffu, q1, off);
            q2 += __shfl_xor_sync(0xffffffffu, q2, off);
        }
        if (lane == 0) {
            float mean = s0 * (1.f / 128.f);
            RS[r * 4 + 0] = mean;
            RS[r * 4 + 1] = rsqrtf(q0 * (1.f / 128.f) - mean * mean + 1e-5f);
            RS[r * 4 + 2] = rsqrtf(q1 * (1.f / 384.f) + 1e-5f);
            RS[r * 4 + 3] = rsqrtf(q2 * (1.f / 640.f) + 1e-5f);
        }
    }
    __syncthreads();

    /* scale + bias + residual -> out */
    for (int r = 0; r < RPB; r++) {
        int n = n0 + r;
        if (n >= N) break;
        float mean = RS[r * 4], inv0 = RS[r * 4 + 1], inv1 = RS[r * 4 + 2], inv2 = RS[r * 4 + 3];
        for (int jj = t; jj < 1152; jj += NT) {
            int p, u, l;
            if (jj < 128)      { l = 0; p = 0; u = jj; }
            else if (jj < 512) { l = 1; int q = jj - 128; u = q / 3; p = 1 + (q - u * 3); }
            else               { l = 2; int q = jj - 512; u = q / 5; p = 4 + (q - u * 5); }
            float val = Bf[r * ROWF + p * PL + u];
            if (l == 0)      val = (val - mean) * inv0 * lnw[u] + lnb[u];
            else if (l == 1) val = val * inv1 * lnw[128 + u];
            else             val = val * inv2 * lnw[256 + u];
            size_t gi = (size_t)n * 1152 + jj;
            out[gi] = val + oldf[gi];
        }
    }
}

extern "C" void kernel_launch(void* const* d_in, const int* in_sizes, int n_in,
                              void* d_out, int out_size) {
    const float* x    = (const float*)d_in[0];
    const float* oldf = (const float*)d_in[1];
    const float* wl   = (const float*)d_in[2];
    const float* bl   = (const float*)d_in[3];
    const float* wr   = (const float*)d_in[4];
    const float* br   = (const float*)d_in[5];
    const float* wp   = (const float*)d_in[6];
    const float* bp   = (const float*)d_in[7];
    const float* tpw  = (const float*)d_in[8];
    const float* lnw  = (const float*)d_in[9];
    const float* lnb  = (const float*)d_in[10];
    float* out = (float*)d_out;
    int N = in_sizes[0] / 1152;

    w3j_init<<<11, 125>>>();

    size_t smem = (size_t)(3 * RPB * ROWF + 128 * PL + 1375 + 1408 + 32) * sizeof(float);
    cudaFuncSetAttribute(self_layer_kernel, cudaFuncAttributeMaxDynamicSharedMemorySize, (int)smem);
    int blocks = (N + RPB - 1) / RPB;
    self_layer_kernel<<<blocks, NT, smem>>>(x, oldf, wl, bl, wr, br, wp, bp, tpw, lnw, lnb, out, N);
}

// round 9
// speedup vs baseline: 1.4272x; 1.4272x over previous
#include <cuda_runtime.h>
#include <math.h>

#define RPB  8
#define NT   256
#define PL   132
#define ROWF 1188          /* 9 planes * 132 */
#define RS_MUL 0.08838834764831845f

__device__ float g_coef[11 * 125];

/* ---------------- W3J init (fp64, replicates reference; proven R6) ------- */
__device__ double dfact(int n) { double r = 1; for (int i = 2; i <= n; i++) r *= i; return r; }

__device__ double cg_d(int j1, int m1, int j2, int m2, int j3, int m3) {
    if (m1 + m2 != m3) return 0.0;
    double pre = sqrt((2.0 * j3 + 1.0) * dfact(j3 + j1 - j2) * dfact(j3 - j1 + j2) *
                      dfact(j1 + j2 - j3) / dfact(j1 + j2 + j3 + 1));
    pre *= sqrt(dfact(j3 + m3) * dfact(j3 - m3) * dfact(j1 - m1) * dfact(j1 + m1) *
                dfact(j2 - m2) * dfact(j2 + m2));
    double s = 0;
    for (int k = 0; k <= j1 + j2 - j3; k++) {
        int d0 = k, d1 = j1 + j2 - j3 - k, d2 = j1 - m1 - k;
        int d3 = j2 + m2 - k, d4 = j3 - j2 + m1 + k, d5 = j3 - j1 - m2 + k;
        if (d0 < 0 || d1 < 0 || d2 < 0 || d3 < 0 || d4 < 0 || d5 < 0) continue;
        double den = dfact(d0) * dfact(d1) * dfact(d2) * dfact(d3) * dfact(d4) * dfact(d5);
        s += ((k & 1) ? -1.0 : 1.0) / den;
    }
    return pre * s;
}

__global__ void w3j_init() {
    __shared__ double Wc[125], Wr[125];
    __shared__ double Qr[3][25], Qi[3][25];
    __shared__ double s_sign;
    const int L1[11] = {0,0,0,1,1,1,1,2,2,2,2};
    const int L2[11] = {0,1,2,0,1,1,2,0,1,2,2};
    const int L3[11] = {0,1,2,1,0,2,1,2,1,0,2};
    const int NP[3] = {3, 4, 4};
    int ins = blockIdx.x;
    int l1 = L1[ins], l2 = L2[ins], l3 = L3[ins];
    int d1 = 2*l1+1, d2 = 2*l2+1, d3 = 2*l3+1;
    int t = threadIdx.x;
    int x = t / 25, y = (t / 5) % 5, z = t % 5;

    if (t == 0) {
        int ls[3] = {l1, l2, l3};
        for (int q = 0; q < 3; q++) {
            int l = ls[q];
            for (int a = 0; a < 25; a++) { Qr[q][a] = 0; Qi[q][a] = 0; }
            Qr[q][l*5 + l] = 1.0;
            double s = 1.0 / sqrt(2.0);
            for (int m = 1; m <= l; m++) {
                double sg = (m & 1) ? -1.0 : 1.0;
                Qr[q][(l+m)*5 + (l-m)] = s;
                Qr[q][(l+m)*5 + (l+m)] = sg * s;
                Qi[q][(l-m)*5 + (l-m)] = s;
                Qi[q][(l-m)*5 + (l+m)] = -sg * s;
            }
        }
    }
    double wc = 0;
    if (x < d1 && y < d2 && z < d3) {
        int m1 = x - l1, m2 = y - l2, m3 = z - l3;
        if (m3 == -(m1 + m2)) {
            int e = l1 - l2 - m3;
            double sg = (e & 1) ? -1.0 : 1.0;
            wc = sg / sqrt(2.0 * l3 + 1.0) * cg_d(l1, m1, l2, m2, l3, -m3);
        }
    }
    Wc[t] = wc;
    __syncthreads();

    double acc = 0;
    if (x < d1 && y < d2 && z < d3) {
        for (int a = 0; a < d1; a++)
            for (int b = 0; b < d2; b++) {
                double q1r = Qr[0][x*5+a], q1i = Qi[0][x*5+a];
                double q2r = Qr[1][y*5+b], q2i = Qi[1][y*5+b];
                double ur = q1r * q2r - q1i * q2i;
                double ui = q1r * q2i + q1i * q2r;
                for (int c = 0; c < d3; c++) {
                    double w = Wc[a*25 + b*5 + c];
                    if (w != 0.0) {
                        double re = ur * Qr[2][z*5+c] - ui * Qi[2][z*5+c];
                        acc += re * w;
                    }
                }
            }
    }
    Wr[t] = acc;
    __syncthreads();

    if (t == 0) {
        double amax = 0;
        for (int a = 0; a < d1; a++) for (int b = 0; b < d2; b++) for (int c = 0; c < d3; c++) {
            double av = fabs(Wr[a*25 + b*5 + c]);
            if (av > amax) amax = av;
        }
        double sg = 1.0; int done = 0;
        for (int a = 0; a < d1; a++) for (int b = 0; b < d2; b++) for (int c = 0; c < d3; c++) {
            double w = Wr[a*25 + b*5 + c];
            if (!done && fabs(w) >= amax * (1.0 - 1e-9)) { sg = (w >= 0) ? 1.0 : -1.0; done = 1; }
        }
        /* (2,2,2): mixed-sign max tie; numpy argmax lands on a negative
           element (verified empirically R5->R6). */
        if (ins == 10) sg = -sg;
        s_sign = sg;
    }
    __syncthreads();

    double pw = sqrt((2.0 * l3 + 1.0) / (double)NP[l3]);
    float o = 0.f;
    if (x < d1 && y < d2 && z < d3) o = (float)(Wr[t] * s_sign * pw);
    g_coef[ins * 125 + t] = o;
}

/* ---------------- Main fused kernel ---------------- */
__device__ __forceinline__ void stage_w(const float* __restrict__ gw, float* wt, int t) {
#pragma unroll
    for (int it = 0; it < 16; ++it) {
        int flat = it * NT + t;           /* 4096 float4 = 128x128 */
        int u = flat >> 5;
        int v4 = (flat & 31) << 2;
        float4 g = *(const float4*)(gw + u * 128 + v4);
        wt[(v4 + 0) * PL + u] = g.x;
        wt[(v4 + 1) * PL + u] = g.y;
        wt[(v4 + 2) * PL + u] = g.z;
        wt[(v4 + 3) * PL + u] = g.w;
    }
}

/* thread = (v0 = t&31, r = t>>5); computes 4 v-columns {v0+32c} of row r */
template <int DIM>
__device__ __forceinline__ void gemm_l(const float* __restrict__ inb, float* __restrict__ outb,
                                       const float* __restrict__ wt,
                                       const float* __restrict__ bias,
                                       int v0, int r, int loff) {
    float acc[4][DIM];
#pragma unroll
    for (int c = 0; c < 4; c++)
#pragma unroll
        for (int i = 0; i < DIM; i++) acc[c][i] = 0.f;

    const float* a0 = inb + r * ROWF + loff;
    const float* w0 = wt + v0 * PL;
#pragma unroll 2
    for (int u = 0; u < 128; u += 4) {
        float4 av[DIM];
#pragma unroll
        for (int i = 0; i < DIM; i++) av[i] = *(const float4*)(a0 + i * PL + u);
        float4 w4[4];
#pragma unroll
        for (int c = 0; c < 4; c++) w4[c] = *(const float4*)(w0 + c * 32 * PL + u);
#pragma unroll
        for (int c = 0; c < 4; c++)
#pragma unroll
            for (int i = 0; i < DIM; i++) {
                acc[c][i] = fmaf(av[i].x, w4[c].x, acc[c][i]);
                acc[c][i] = fmaf(av[i].y, w4[c].y, acc[c][i]);
                acc[c][i] = fmaf(av[i].z, w4[c].z, acc[c][i]);
                acc[c][i] = fmaf(av[i].w, w4[c].w, acc[c][i]);
            }
    }
#pragma unroll
    for (int c = 0; c < 4; c++) {
        int v = v0 + 32 * c;
        float bv = bias ? bias[v] : 0.f;
#pragma unroll
        for (int i = 0; i < DIM; i++)
            outb[r * ROWF + loff + i * PL + v] = acc[c][i] * RS_MUL + bv;
    }
}

#define TP_INS(n, D1, D2, D3, B1, B2, B3)                                   \
    do {                                                                    \
        float w_ = TW[(n)*128 + u];                                         \
        _Pragma("unroll") for (int xx = 0; xx < (D1); xx++)                 \
        _Pragma("unroll") for (int yy = 0; yy < (D2); yy++) {               \
            float t2 = w_ * cl[(B1) + xx] * cr[(B2) + yy];                  \
            _Pragma("unroll") for (int zz = 0; zz < (D3); zz++)             \
                o[(B3) + zz] = fmaf(t2, CF[(n)*125 + xx*25 + yy*5 + zz],    \
                                    o[(B3) + zz]);                          \
        }                                                                   \
    } while (0)

__global__ void __launch_bounds__(NT, 1)
self_layer_kernel(const float* __restrict__ x, const float* __restrict__ oldf,
                  const float* __restrict__ wl, const float* __restrict__ bl,
                  const float* __restrict__ wr, const float* __restrict__ br,
                  const float* __restrict__ wp, const float* __restrict__ bp,
                  const float* __restrict__ tpw, const float* __restrict__ lnw,
                  const float* __restrict__ lnb, float* __restrict__ out, int N) {
    extern __shared__ float sm[];
    float* A  = sm;                  /* 8*1188 */
    float* Bf = A + RPB * ROWF;
    float* Cf = Bf + RPB * ROWF;
    float* WT = Cf + RPB * ROWF;     /* 128*132 */
    float* CF = WT + 128 * PL;       /* 1375 */
    float* TW = CF + 1375;           /* 1408 */
    float* RS = TW + 1408;           /* 32 */

    int t = threadIdx.x;
    int n0 = blockIdx.x * RPB;

    /* load x -> planar A */
    for (int idx = t; idx < RPB * 1152; idx += NT) {
        int r = idx / 1152, jj = idx - r * 1152;
        int n = n0 + r;
        float val = (n < N) ? x[(size_t)n * 1152 + jj] : 0.f;
        int p, u;
        if (jj < 128)      { p = 0; u = jj; }
        else if (jj < 512) { int q = jj - 128; u = q / 3; p = 1 + (q - u * 3); }
        else               { int q = jj - 512; u = q / 5; p = 4 + (q - u * 5); }
        A[r * ROWF + p * PL + u] = val;
    }
    for (int i = t; i < 1375; i += NT) CF[i] = g_coef[i];
    for (int i = t; i < 1408; i += NT) TW[i] = tpw[i];
    __syncthreads();

    int v0 = t & 31, rr = t >> 5;    /* 32 v-threads x 8 rows */

    /* lin_l : A -> Bf */
    stage_w(wl,         WT, t); __syncthreads(); gemm_l<1>(A, Bf, WT, bl, v0, rr, 0);      __syncthreads();
    stage_w(wl + 16384, WT, t); __syncthreads(); gemm_l<3>(A, Bf, WT, 0,  v0, rr, PL);     __syncthreads();
    stage_w(wl + 32768, WT, t); __syncthreads(); gemm_l<5>(A, Bf, WT, 0,  v0, rr, 4 * PL); __syncthreads();
    /* lin_r : A -> Cf */
    stage_w(wr,         WT, t); __syncthreads(); gemm_l<1>(A, Cf, WT, br, v0, rr, 0);      __syncthreads();
    stage_w(wr + 16384, WT, t); __syncthreads(); gemm_l<3>(A, Cf, WT, 0,  v0, rr, PL);     __syncthreads();
    stage_w(wr + 32768, WT, t); __syncthreads(); gemm_l<5>(A, Cf, WT, 0,  v0, rr, 4 * PL); __syncthreads();

    /* tensor product: Bf,Cf -> A  (RPB*128 = 1024 items, 4 passes) */
#pragma unroll 1
    for (int it = 0; it < 4; ++it) {
        int idx = it * NT + t;
        int r = idx >> 7, u = idx & 127;
        int base = r * ROWF + u;
        float cl[9], cr[9], o[9];
#pragma unroll
        for (int c = 0; c < 9; c++) { cl[c] = Bf[base + c * PL]; cr[c] = Cf[base + c * PL]; o[c] = 0.f; }
        TP_INS(0, 1, 1, 1, 0, 0, 0);
        TP_INS(1, 1, 3, 3, 0, 1, 1);
        TP_INS(2, 1, 5, 5, 0, 4, 4);
        TP_INS(3, 3, 1, 3, 1, 0, 1);
        TP_INS(4, 3, 3, 1, 1, 1, 0);
        TP_INS(5, 3, 3, 5, 1, 1, 4);
        TP_INS(6, 3, 5, 3, 1, 4, 1);
        TP_INS(7, 5, 1, 5, 4, 0, 4);
        TP_INS(8, 5, 3, 3, 4, 1, 1);
        TP_INS(9, 5, 5, 1, 4, 4, 0);
        TP_INS(10, 5, 5, 5, 4, 4, 4);
#pragma unroll
        for (int c = 0; c < 9; c++) A[base + c * PL] = o[c];
    }
    __syncthreads();

    /* lin_p : A -> Bf */
    stage_w(wp,         WT, t); __syncthreads(); gemm_l<1>(A, Bf, WT, bp, v0, rr, 0);      __syncthreads();
    stage_w(wp + 16384, WT, t); __syncthreads(); gemm_l<3>(A, Bf, WT, 0,  v0, rr, PL);     __syncthreads();
    stage_w(wp + 32768, WT, t); __syncthreads(); gemm_l<5>(A, Bf, WT, 0,  v0, rr, 4 * PL); __syncthreads();

    /* e3norm stats: one warp per row (exactly 8 warps, 8 rows) */
    int wid = t >> 5, lane = t & 31;
    {
        int r = wid;
        const float* fr = Bf + r * ROWF;
        float s0 = 0, q0 = 0, q1 = 0, q2 = 0;
        {
            float4 a = *(const float4*)(fr + lane * 4);
            s0 = a.x + a.y + a.z + a.w;
            q0 = a.x * a.x + a.y * a.y + a.z * a.z + a.w * a.w;
        }
#pragma unroll
        for (int p = 1; p < 4; p++) {
            float4 a = *(const float4*)(fr + p * PL + lane * 4);
            q1 += a.x * a.x + a.y * a.y + a.z * a.z + a.w * a.w;
        }
#pragma unroll
        for (int p = 4; p < 9; p++) {
            float4 a = *(const float4*)(fr + p * PL + lane * 4);
            q2 += a.x * a.x + a.y * a.y + a.z * a.z + a.w * a.w;
        }
#pragma unroll
        for (int off = 16; off; off >>= 1) {
            s0 += __shfl_xor_sync(0xffffffffu, s0, off);
            q0 += __shfl_xor_sync(0xffffffffu, q0, off);
            q1 += __shfl_xor_sync(0xffffffffu, q1, off);
            q2 += __shfl_xor_sync(0xffffffffu, q2, off);
        }
        if (lane == 0) {
            float mean = s0 * (1.f / 128.f);
            RS[r * 4 + 0] = mean;
            RS[r * 4 + 1] = rsqrtf(q0 * (1.f / 128.f) - mean * mean + 1e-5f);
            RS[r * 4 + 2] = rsqrtf(q1 * (1.f / 384.f) + 1e-5f);
            RS[r * 4 + 3] = rsqrtf(q2 * (1.f / 640.f) + 1e-5f);
        }
    }
    __syncthreads();

    /* scale + bias + residual -> out */
    for (int r = 0; r < RPB; r++) {
        int n = n0 + r;
        if (n >= N) break;
        float mean = RS[r * 4], inv0 = RS[r * 4 + 1], inv1 = RS[r * 4 + 2], inv2 = RS[r * 4 + 3];
        for (int jj = t; jj < 1152; jj += NT) {
            int p, u, l;
            if (jj < 128)      { l = 0; p = 0; u = jj; }
            else if (jj < 512) { l = 1; int q = jj - 128; u = q / 3; p = 1 + (q - u * 3); }
            else               { l = 2; int q = jj - 512; u = q / 5; p = 4 + (q - u * 5); }
            float val = Bf[r * ROWF + p * PL + u];
            if (l == 0)      val = (val - mean) * inv0 * lnw[u] + lnb[u];
            else if (l == 1) val = val * inv1 * lnw[128 + u];
            else             val = val * inv2 * lnw[256 + u];
            size_t gi = (size_t)n * 1152 + jj;
            out[gi] = val + oldf[gi];
        }
    }
}

extern "C" void kernel_launch(void* const* d_in, const int* in_sizes, int n_in,
                              void* d_out, int out_size) {
    const float* x    = (const float*)d_in[0];
    const float* oldf = (const float*)d_in[1];
    const float* wl   = (const float*)d_in[2];
    const float* bl   = (const float*)d_in[3];
    const float* wr   = (const float*)d_in[4];
    const float* br   = (const float*)d_in[5];
    const float* wp   = (const float*)d_in[6];
    const float* bp   = (const float*)d_in[7];
    const float* tpw  = (const float*)d_in[8];
    const float* lnw  = (const float*)d_in[9];
    const float* lnb  = (const float*)d_in[10];
    float* out = (float*)d_out;
    int N = in_sizes[0] / 1152;

    w3j_init<<<11, 125>>>();

    size_t smem = (size_t)(3 * RPB * ROWF + 128 * PL + 1375 + 1408 + 32) * sizeof(float);
    cudaFuncSetAttribute(self_layer_kernel, cudaFuncAttributeMaxDynamicSharedMemorySize, (int)smem);
    int blocks = (N + RPB - 1) / RPB;
    self_layer_kernel<<<blocks, NT, smem>>>(x, oldf, wl, bl, wr, br, wp, bp, tpw, lnw, lnb, out, N);
}

// round 10
// speedup vs baseline: 1.4526x; 1.0178x over previous
#include <cuda_runtime.h>
#include <math.h>

#define RPB  8
#define NT   256
#define PL   132
#define ROWF 1188          /* 9 planes * 132 */
#define RS_MUL 0.08838834764831845f

__device__ float g_coef[11 * 125];

/* ---------------- W3J init (fp64, replicates reference; proven R6) ------- */
__device__ double dfact(int n) { double r = 1; for (int i = 2; i <= n; i++) r *= i; return r; }

__device__ double cg_d(int j1, int m1, int j2, int m2, int j3, int m3) {
    if (m1 + m2 != m3) return 0.0;
    double pre = sqrt((2.0 * j3 + 1.0) * dfact(j3 + j1 - j2) * dfact(j3 - j1 + j2) *
                      dfact(j1 + j2 - j3) / dfact(j1 + j2 + j3 + 1));
    pre *= sqrt(dfact(j3 + m3) * dfact(j3 - m3) * dfact(j1 - m1) * dfact(j1 + m1) *
                dfact(j2 - m2) * dfact(j2 + m2));
    double s = 0;
    for (int k = 0; k <= j1 + j2 - j3; k++) {
        int d0 = k, d1 = j1 + j2 - j3 - k, d2 = j1 - m1 - k;
        int d3 = j2 + m2 - k, d4 = j3 - j2 + m1 + k, d5 = j3 - j1 - m2 + k;
        if (d0 < 0 || d1 < 0 || d2 < 0 || d3 < 0 || d4 < 0 || d5 < 0) continue;
        double den = dfact(d0) * dfact(d1) * dfact(d2) * dfact(d3) * dfact(d4) * dfact(d5);
        s += ((k & 1) ? -1.0 : 1.0) / den;
    }
    return pre * s;
}

__global__ void w3j_init() {
    __shared__ double Wc[125], Wr[125];
    __shared__ double Qr[3][25], Qi[3][25];
    __shared__ double s_sign;
    const int L1[11] = {0,0,0,1,1,1,1,2,2,2,2};
    const int L2[11] = {0,1,2,0,1,1,2,0,1,2,2};
    const int L3[11] = {0,1,2,1,0,2,1,2,1,0,2};
    const int NP[3] = {3, 4, 4};
    int ins = blockIdx.x;
    int l1 = L1[ins], l2 = L2[ins], l3 = L3[ins];
    int d1 = 2*l1+1, d2 = 2*l2+1, d3 = 2*l3+1;
    int t = threadIdx.x;
    int x = t / 25, y = (t / 5) % 5, z = t % 5;

    if (t == 0) {
        int ls[3] = {l1, l2, l3};
        for (int q = 0; q < 3; q++) {
            int l = ls[q];
            for (int a = 0; a < 25; a++) { Qr[q][a] = 0; Qi[q][a] = 0; }
            Qr[q][l*5 + l] = 1.0;
            double s = 1.0 / sqrt(2.0);
            for (int m = 1; m <= l; m++) {
                double sg = (m & 1) ? -1.0 : 1.0;
                Qr[q][(l+m)*5 + (l-m)] = s;
                Qr[q][(l+m)*5 + (l+m)] = sg * s;
                Qi[q][(l-m)*5 + (l-m)] = s;
                Qi[q][(l-m)*5 + (l+m)] = -sg * s;
            }
        }
    }
    double wc = 0;
    if (x < d1 && y < d2 && z < d3) {
        int m1 = x - l1, m2 = y - l2, m3 = z - l3;
        if (m3 == -(m1 + m2)) {
            int e = l1 - l2 - m3;
            double sg = (e & 1) ? -1.0 : 1.0;
            wc = sg / sqrt(2.0 * l3 + 1.0) * cg_d(l1, m1, l2, m2, l3, -m3);
        }
    }
    Wc[t] = wc;
    __syncthreads();

    double acc = 0;
    if (x < d1 && y < d2 && z < d3) {
        for (int a = 0; a < d1; a++)
            for (int b = 0; b < d2; b++) {
                double q1r = Qr[0][x*5+a], q1i = Qi[0][x*5+a];
                double q2r = Qr[1][y*5+b], q2i = Qi[1][y*5+b];
                double ur = q1r * q2r - q1i * q2i;
                double ui = q1r * q2i + q1i * q2r;
                for (int c = 0; c < d3; c++) {
                    double w = Wc[a*25 + b*5 + c];
                    if (w != 0.0) {
                        double re = ur * Qr[2][z*5+c] - ui * Qi[2][z*5+c];
                        acc += re * w;
                    }
                }
            }
    }
    Wr[t] = acc;
    __syncthreads();

    if (t == 0) {
        double amax = 0;
        for (int a = 0; a < d1; a++) for (int b = 0; b < d2; b++) for (int c = 0; c < d3; c++) {
            double av = fabs(Wr[a*25 + b*5 + c]);
            if (av > amax) amax = av;
        }
        double sg = 1.0; int done = 0;
        for (int a = 0; a < d1; a++) for (int b = 0; b < d2; b++) for (int c = 0; c < d3; c++) {
            double w = Wr[a*25 + b*5 + c];
            if (!done && fabs(w) >= amax * (1.0 - 1e-9)) { sg = (w >= 0) ? 1.0 : -1.0; done = 1; }
        }
        /* (2,2,2): mixed-sign max tie; numpy argmax lands on a negative
           element (verified empirically R5->R6). */
        if (ins == 10) sg = -sg;
        s_sign = sg;
    }
    __syncthreads();

    double pw = sqrt((2.0 * l3 + 1.0) / (double)NP[l3]);
    float o = 0.f;
    if (x < d1 && y < d2 && z < d3) o = (float)(Wr[t] * s_sign * pw);
    g_coef[ins * 125 + t] = o;
}

/* ---------------- Main fused kernel ---------------- */
/* Stage weights in NATIVE [u][v] layout (row stride PL): coalesced global
   float4 read, conflict-free consecutive STS.128. No transpose. */
__device__ __forceinline__ void stage_w(const float* __restrict__ gw, float* wt, int t) {
#pragma unroll
    for (int it = 0; it < 16; ++it) {
        int flat = it * NT + t;           /* 4096 float4 = 128x128 */
        int u = flat >> 5;
        int v4 = (flat & 31) << 2;
        *(float4*)(wt + u * PL + v4) = *(const float4*)(gw + u * 128 + v4);
    }
}

/* thread = (lane = t&31, r = t>>5); computes v-quad {4*lane..4*lane+3} of row r.
   Weight reads: WT[(u+j)*PL + 4*lane] float4 -> lanes consecutive, conflict-free.
   A reads: broadcast float4 along u. */
template <int DIM>
__device__ __forceinline__ void gemm_l(const float* __restrict__ inb, float* __restrict__ outb,
                                       const float* __restrict__ wt,
                                       const float* __restrict__ bias,
                                       int lane, int r, int loff) {
    float acc[4][DIM];
#pragma unroll
    for (int c = 0; c < 4; c++)
#pragma unroll
        for (int i = 0; i < DIM; i++) acc[c][i] = 0.f;

    const float* a0 = inb + r * ROWF + loff;
    const float* w0 = wt + lane * 4;
#pragma unroll 2
    for (int u = 0; u < 128; u += 4) {
        float4 av[DIM];
#pragma unroll
        for (int i = 0; i < DIM; i++) av[i] = *(const float4*)(a0 + i * PL + u);
        float4 wq[4];
#pragma unroll
        for (int j = 0; j < 4; j++) wq[j] = *(const float4*)(w0 + (u + j) * PL);
#pragma unroll
        for (int j = 0; j < 4; j++) {
            float4 w4 = wq[j];
#pragma unroll
            for (int i = 0; i < DIM; i++) {
                float a = ((const float*)&av[i])[j];
                acc[0][i] = fmaf(a, w4.x, acc[0][i]);
                acc[1][i] = fmaf(a, w4.y, acc[1][i]);
                acc[2][i] = fmaf(a, w4.z, acc[2][i]);
                acc[3][i] = fmaf(a, w4.w, acc[3][i]);
            }
        }
    }
    int v = lane * 4;
    float4 bv = make_float4(0.f, 0.f, 0.f, 0.f);
    if (bias) bv = *(const float4*)(bias + v);
#pragma unroll
    for (int i = 0; i < DIM; i++) {
        float4 o;
        o.x = acc[0][i] * RS_MUL + bv.x;
        o.y = acc[1][i] * RS_MUL + bv.y;
        o.z = acc[2][i] * RS_MUL + bv.z;
        o.w = acc[3][i] * RS_MUL + bv.w;
        *(float4*)(outb + r * ROWF + loff + i * PL + v) = o;
    }
}

#define TP_INS(n, D1, D2, D3, B1, B2, B3)                                   \
    do {                                                                    \
        float w_ = TW[(n)*128 + u];                                         \
        _Pragma("unroll") for (int xx = 0; xx < (D1); xx++)                 \
        _Pragma("unroll") for (int yy = 0; yy < (D2); yy++) {               \
            float t2 = w_ * cl[(B1) + xx] * cr[(B2) + yy];                  \
            _Pragma("unroll") for (int zz = 0; zz < (D3); zz++)             \
                o[(B3) + zz] = fmaf(t2, CF[(n)*125 + xx*25 + yy*5 + zz],    \
                                    o[(B3) + zz]);                          \
        }                                                                   \
    } while (0)

__global__ void __launch_bounds__(NT, 1)
self_layer_kernel(const float* __restrict__ x, const float* __restrict__ oldf,
                  const float* __restrict__ wl, const float* __restrict__ bl,
                  const float* __restrict__ wr, const float* __restrict__ br,
                  const float* __restrict__ wp, const float* __restrict__ bp,
                  const float* __restrict__ tpw, const float* __restrict__ lnw,
                  const float* __restrict__ lnb, float* __restrict__ out, int N) {
    extern __shared__ float sm[];
    float* A  = sm;                  /* 8*1188 */
    float* Bf = A + RPB * ROWF;
    float* Cf = Bf + RPB * ROWF;
    float* WT = Cf + RPB * ROWF;     /* 128*132 (native [u][v], pad 4) */
    float* CF = WT + 128 * PL;       /* 1375 */
    float* TW = CF + 1375;           /* 1408 */
    float* RS = TW + 1408;           /* 32 */

    int t = threadIdx.x;
    int n0 = blockIdx.x * RPB;

    /* load x -> planar A */
    for (int idx = t; idx < RPB * 1152; idx += NT) {
        int r = idx / 1152, jj = idx - r * 1152;
        int n = n0 + r;
        float val = (n < N) ? x[(size_t)n * 1152 + jj] : 0.f;
        int p, u;
        if (jj < 128)      { p = 0; u = jj; }
        else if (jj < 512) { int q = jj - 128; u = q / 3; p = 1 + (q - u * 3); }
        else               { int q = jj - 512; u = q / 5; p = 4 + (q - u * 5); }
        A[r * ROWF + p * PL + u] = val;
    }
    for (int i = t; i < 1375; i += NT) CF[i] = g_coef[i];
    for (int i = t; i < 1408; i += NT) TW[i] = tpw[i];
    __syncthreads();

    int lane = t & 31, rr = t >> 5;  /* 32 v-quads x 8 rows */

    /* lin_l : A -> Bf */
    stage_w(wl,         WT, t); __syncthreads(); gemm_l<1>(A, Bf, WT, bl, lane, rr, 0);      __syncthreads();
    stage_w(wl + 16384, WT, t); __syncthreads(); gemm_l<3>(A, Bf, WT, 0,  lane, rr, PL);     __syncthreads();
    stage_w(wl + 32768, WT, t); __syncthreads(); gemm_l<5>(A, Bf, WT, 0,  lane, rr, 4 * PL); __syncthreads();
    /* lin_r : A -> Cf */
    stage_w(wr,         WT, t); __syncthreads(); gemm_l<1>(A, Cf, WT, br, lane, rr, 0);      __syncthreads();
    stage_w(wr + 16384, WT, t); __syncthreads(); gemm_l<3>(A, Cf, WT, 0,  lane, rr, PL);     __syncthreads();
    stage_w(wr + 32768, WT, t); __syncthreads(); gemm_l<5>(A, Cf, WT, 0,  lane, rr, 4 * PL); __syncthreads();

    /* tensor product: Bf,Cf -> A  (RPB*128 = 1024 items, 4 passes) */
#pragma unroll 1
    for (int it = 0; it < 4; ++it) {
        int idx = it * NT + t;
        int r = idx >> 7, u = idx & 127;
        int base = r * ROWF + u;
        float cl[9], cr[9], o[9];
#pragma unroll
        for (int c = 0; c < 9; c++) { cl[c] = Bf[base + c * PL]; cr[c] = Cf[base + c * PL]; o[c] = 0.f; }
        TP_INS(0, 1, 1, 1, 0, 0, 0);
        TP_INS(1, 1, 3, 3, 0, 1, 1);
        TP_INS(2, 1, 5, 5, 0, 4, 4);
        TP_INS(3, 3, 1, 3, 1, 0, 1);
        TP_INS(4, 3, 3, 1, 1, 1, 0);
        TP_INS(5, 3, 3, 5, 1, 1, 4);
        TP_INS(6, 3, 5, 3, 1, 4, 1);
        TP_INS(7, 5, 1, 5, 4, 0, 4);
        TP_INS(8, 5, 3, 3, 4, 1, 1);
        TP_INS(9, 5, 5, 1, 4, 4, 0);
        TP_INS(10, 5, 5, 5, 4, 4, 4);
#pragma unroll
        for (int c = 0; c < 9; c++) A[base + c * PL] = o[c];
    }
    __syncthreads();

    /* lin_p : A -> Bf */
    stage_w(wp,         WT, t); __syncthreads(); gemm_l<1>(A, Bf, WT, bp, lane, rr, 0);      __syncthreads();
    stage_w(wp + 16384, WT, t); __syncthreads(); gemm_l<3>(A, Bf, WT, 0,  lane, rr, PL);     __syncthreads();
    stage_w(wp + 32768, WT, t); __syncthreads(); gemm_l<5>(A, Bf, WT, 0,  lane, rr, 4 * PL); __syncthreads();

    /* e3norm stats: one warp per row (exactly 8 warps, 8 rows) */
    int wid = t >> 5, ln = t & 31;
    {
        int r = wid;
        const float* fr = Bf + r * ROWF;
        float s0 = 0, q0 = 0, q1 = 0, q2 = 0;
        {
            float4 a = *(const float4*)(fr + ln * 4);
            s0 = a.x + a.y + a.z + a.w;
            q0 = a.x * a.x + a.y * a.y + a.z * a.z + a.w * a.w;
        }
#pragma unroll
        for (int p = 1; p < 4; p++) {
            float4 a = *(const float4*)(fr + p * PL + ln * 4);
            q1 += a.x * a.x + a.y * a.y + a.z * a.z + a.w * a.w;
        }
#pragma unroll
        for (int p = 4; p < 9; p++) {
            float4 a = *(const float4*)(fr + p * PL + ln * 4);
            q2 += a.x * a.x + a.y * a.y + a.z * a.z + a.w * a.w;
        }
#pragma unroll
        for (int off = 16; off; off >>= 1) {
            s0 += __shfl_xor_sync(0xffffffffu, s0, off);
            q0 += __shfl_xor_sync(0xffffffffu, q0, off);
            q1 += __shfl_xor_sync(0xffffffffu, q1, off);
            q2 += __shfl_xor_sync(0xffffffffu, q2, off);
        }
        if (ln == 0) {
            float mean = s0 * (1.f / 128.f);
            RS[r * 4 + 0] = mean;
            RS[r * 4 + 1] = rsqrtf(q0 * (1.f / 128.f) - mean * mean + 1e-5f);
            RS[r * 4 + 2] = rsqrtf(q1 * (1.f / 384.f) + 1e-5f);
            RS[r * 4 + 3] = rsqrtf(q2 * (1.f / 640.f) + 1e-5f);
        }
    }
    __syncthreads();

    /* scale + bias + residual -> out */
    for (int r = 0; r < RPB; r++) {
        int n = n0 + r;
        if (n >= N) break;
        float mean = RS[r * 4], inv0 = RS[r * 4 + 1], inv1 = RS[r * 4 + 2], inv2 = RS[r * 4 + 3];
        for (int jj = t; jj < 1152; jj += NT) {
            int p, u, l;
            if (jj < 128)      { l = 0; p = 0; u = jj; }
            else if (jj < 512) { l = 1; int q = jj - 128; u = q / 3; p = 1 + (q - u * 3); }
            else               { l = 2; int q = jj - 512; u = q / 5; p = 4 + (q - u * 5); }
            float val = Bf[r * ROWF + p * PL + u];
            if (l == 0)      val = (val - mean) * inv0 * lnw[u] + lnb[u];
            else if (l == 1) val = val * inv1 * lnw[128 + u];
            else             val = val * inv2 * lnw[256 + u];
            size_t gi = (size_t)n * 1152 + jj;
            out[gi] = val + oldf[gi];
        }
    }
}

extern "C" void kernel_launch(void* const* d_in, const int* in_sizes, int n_in,
                              void* d_out, int out_size) {
    const float* x    = (const float*)d_in[0];
    const float* oldf = (const float*)d_in[1];
    const float* wl   = (const float*)d_in[2];
    const float* bl   = (const float*)d_in[3];
    const float* wr   = (const float*)d_in[4];
    const float* br   = (const float*)d_in[5];
    const float* wp   = (const float*)d_in[6];
    const float* bp   = (const float*)d_in[7];
    const float* tpw  = (const float*)d_in[8];
    const float* lnw  = (const float*)d_in[9];
    const float* lnb  = (const float*)d_in[10];
    float* out = (float*)d_out;
    int N = in_sizes[0] / 1152;

    w3j_init<<<11, 125>>>();

    size_t smem = (size_t)(3 * RPB * ROWF + 128 * PL + 1375 + 1408 + 32) * sizeof(float);
    cudaFuncSetAttribute(self_layer_kernel, cudaFuncAttributeMaxDynamicSharedMemorySize, (int)smem);
    int blocks = (N + RPB - 1) / RPB;
    self_layer_kernel<<<blocks, NT, smem>>>(x, oldf, wl, bl, wr, br, wp, bp, tpw, lnw, lnb, out, N);
}

// round 11
// speedup vs baseline: 2.1785x; 1.4997x over previous
#include <cuda_runtime.h>
#include <math.h>

#define RPB  10
#define NT   320
#define PL   132
#define ROWF 1188          /* 9 planes * 132 */
#define RS_MUL 0.08838834764831845f

typedef unsigned long long u64;

__device__ float g_coef[11 * 125];

/* ---------------- W3J init (fp64, replicates reference; proven R6) ------- */
__device__ double dfact(int n) { double r = 1; for (int i = 2; i <= n; i++) r *= i; return r; }

__device__ double cg_d(int j1, int m1, int j2, int m2, int j3, int m3) {
    if (m1 + m2 != m3) return 0.0;
    double pre = sqrt((2.0 * j3 + 1.0) * dfact(j3 + j1 - j2) * dfact(j3 - j1 + j2) *
                      dfact(j1 + j2 - j3) / dfact(j1 + j2 + j3 + 1));
    pre *= sqrt(dfact(j3 + m3) * dfact(j3 - m3) * dfact(j1 - m1) * dfact(j1 + m1) *
                dfact(j2 - m2) * dfact(j2 + m2));
    double s = 0;
    for (int k = 0; k <= j1 + j2 - j3; k++) {
        int d0 = k, d1 = j1 + j2 - j3 - k, d2 = j1 - m1 - k;
        int d3 = j2 + m2 - k, d4 = j3 - j2 + m1 + k, d5 = j3 - j1 - m2 + k;
        if (d0 < 0 || d1 < 0 || d2 < 0 || d3 < 0 || d4 < 0 || d5 < 0) continue;
        double den = dfact(d0) * dfact(d1) * dfact(d2) * dfact(d3) * dfact(d4) * dfact(d5);
        s += ((k & 1) ? -1.0 : 1.0) / den;
    }
    return pre * s;
}

__global__ void w3j_init() {
    __shared__ double Wc[125], Wr[125];
    __shared__ double Qr[3][25], Qi[3][25];
    __shared__ double s_sign;
    const int L1[11] = {0,0,0,1,1,1,1,2,2,2,2};
    const int L2[11] = {0,1,2,0,1,1,2,0,1,2,2};
    const int L3[11] = {0,1,2,1,0,2,1,2,1,0,2};
    const int NP[3] = {3, 4, 4};
    int ins = blockIdx.x;
    int l1 = L1[ins], l2 = L2[ins], l3 = L3[ins];
    int d1 = 2*l1+1, d2 = 2*l2+1, d3 = 2*l3+1;
    int t = threadIdx.x;
    int x = t / 25, y = (t / 5) % 5, z = t % 5;

    if (t == 0) {
        int ls[3] = {l1, l2, l3};
        for (int q = 0; q < 3; q++) {
            int l = ls[q];
            for (int a = 0; a < 25; a++) { Qr[q][a] = 0; Qi[q][a] = 0; }
            Qr[q][l*5 + l] = 1.0;
            double s = 1.0 / sqrt(2.0);
            for (int m = 1; m <= l; m++) {
                double sg = (m & 1) ? -1.0 : 1.0;
                Qr[q][(l+m)*5 + (l-m)] = s;
                Qr[q][(l+m)*5 + (l+m)] = sg * s;
                Qi[q][(l-m)*5 + (l-m)] = s;
                Qi[q][(l-m)*5 + (l+m)] = -sg * s;
            }
        }
    }
    double wc = 0;
    if (x < d1 && y < d2 && z < d3) {
        int m1 = x - l1, m2 = y - l2, m3 = z - l3;
        if (m3 == -(m1 + m2)) {
            int e = l1 - l2 - m3;
            double sg = (e & 1) ? -1.0 : 1.0;
            wc = sg / sqrt(2.0 * l3 + 1.0) * cg_d(l1, m1, l2, m2, l3, -m3);
        }
    }
    Wc[t] = wc;
    __syncthreads();

    double acc = 0;
    if (x < d1 && y < d2 && z < d3) {
        for (int a = 0; a < d1; a++)
            for (int b = 0; b < d2; b++) {
                double q1r = Qr[0][x*5+a], q1i = Qi[0][x*5+a];
                double q2r = Qr[1][y*5+b], q2i = Qi[1][y*5+b];
                double ur = q1r * q2r - q1i * q2i;
                double ui = q1r * q2i + q1i * q2r;
                for (int c = 0; c < d3; c++) {
                    double w = Wc[a*25 + b*5 + c];
                    if (w != 0.0) {
                        double re = ur * Qr[2][z*5+c] - ui * Qi[2][z*5+c];
                        acc += re * w;
                    }
                }
            }
    }
    Wr[t] = acc;
    __syncthreads();

    if (t == 0) {
        double amax = 0;
        for (int a = 0; a < d1; a++) for (int b = 0; b < d2; b++) for (int c = 0; c < d3; c++) {
            double av = fabs(Wr[a*25 + b*5 + c]);
            if (av > amax) amax = av;
        }
        double sg = 1.0; int done = 0;
        for (int a = 0; a < d1; a++) for (int b = 0; b < d2; b++) for (int c = 0; c < d3; c++) {
            double w = Wr[a*25 + b*5 + c];
            if (!done && fabs(w) >= amax * (1.0 - 1e-9)) { sg = (w >= 0) ? 1.0 : -1.0; done = 1; }
        }
        /* (2,2,2): mixed-sign max tie; numpy argmax lands on a negative
           element (verified empirically R5->R6). */
        if (ins == 10) sg = -sg;
        s_sign = sg;
    }
    __syncthreads();

    double pw = sqrt((2.0 * l3 + 1.0) / (double)NP[l3]);
    float o = 0.f;
    if (x < d1 && y < d2 && z < d3) o = (float)(Wr[t] * s_sign * pw);
    g_coef[ins * 125 + t] = o;
}

/* ---------------- f32x2 helpers ---------------- */
__device__ __forceinline__ u64 ffma2(u64 a, u64 b, u64 c) {
    u64 d;
    asm("fma.rn.f32x2 %0, %1, %2, %3;" : "=l"(d) : "l"(a), "l"(b), "l"(c));
    return d;
}
__device__ __forceinline__ float hadd2(u64 v) {
    float lo, hi;
    asm("mov.b64 {%0,%1}, %2;" : "=f"(lo), "=f"(hi) : "l"(v));
    return lo + hi;
}

/* ---------------- Main fused kernel ---------------- */
/* Stage weights pair-major: WT2[u2][v] = {w[2u2][v], w[2u2+1][v]} (float2). */
__device__ __forceinline__ void stage_w2(const float* __restrict__ gw, float* wt2, int t) {
    for (int flat = t; flat < 8192; flat += NT) {
        int v = flat & 127, u2 = flat >> 7;
        float2 w;
        w.x = gw[(2 * u2) * 128 + v];
        w.y = gw[(2 * u2 + 1) * 128 + v];
        *(float2*)(wt2 + (u2 * 128 + v) * 2) = w;
    }
}

/* warp w: rowpair rp = w%5 (rows 2rp,2rp+1), kslice ks = w/5 (u in [64ks,64ks+64)).
   lane computes v = lane + 32c, c = 0..3. ks1 writes raw partial to outb;
   after sync ks0 adds its partial, applies RS_MUL + bias, writes final. */
template <int DIM>
__device__ __forceinline__ void gemm2(const float* __restrict__ inb, float* __restrict__ outb,
                                      const float* __restrict__ wt2,
                                      const float* __restrict__ bias,
                                      int lane, int rp, int ks, int loff) {
    u64 acc[2][4][DIM];
#pragma unroll
    for (int rr = 0; rr < 2; rr++)
#pragma unroll
        for (int c = 0; c < 4; c++)
#pragma unroll
            for (int i = 0; i < DIM; i++) acc[rr][c][i] = 0ull;

    const float* a0 = inb + (2 * rp) * ROWF + loff;
    int ub = ks * 64;
#pragma unroll 4
    for (int u = ub; u < ub + 64; u += 4) {
        u64 a[2][DIM][2];
#pragma unroll
        for (int rr = 0; rr < 2; rr++)
#pragma unroll
            for (int i = 0; i < DIM; i++) {
                a[rr][i][0] = *(const u64*)(a0 + rr * ROWF + i * PL + u);
                a[rr][i][1] = *(const u64*)(a0 + rr * ROWF + i * PL + u + 2);
            }
        u64 w[2][4];
#pragma unroll
        for (int p = 0; p < 2; p++)
#pragma unroll
            for (int c = 0; c < 4; c++)
                w[p][c] = *(const u64*)(wt2 + (((u >> 1) + p) * 128 + lane + 32 * c) * 2);
#pragma unroll
        for (int rr = 0; rr < 2; rr++)
#pragma unroll
            for (int c = 0; c < 4; c++)
#pragma unroll
                for (int i = 0; i < DIM; i++) {
                    acc[rr][c][i] = ffma2(a[rr][i][0], w[0][c], acc[rr][c][i]);
                    acc[rr][c][i] = ffma2(a[rr][i][1], w[1][c], acc[rr][c][i]);
                }
    }

    if (ks == 1) {
#pragma unroll
        for (int rr = 0; rr < 2; rr++)
#pragma unroll
            for (int c = 0; c < 4; c++)
#pragma unroll
                for (int i = 0; i < DIM; i++)
                    outb[(2 * rp + rr) * ROWF + loff + i * PL + lane + 32 * c] = hadd2(acc[rr][c][i]);
    }
    __syncthreads();
    if (ks == 0) {
#pragma unroll
        for (int c = 0; c < 4; c++) {
            int v = lane + 32 * c;
            float bv = bias ? bias[v] : 0.f;
#pragma unroll
            for (int rr = 0; rr < 2; rr++)
#pragma unroll
                for (int i = 0; i < DIM; i++) {
                    int idx = (2 * rp + rr) * ROWF + loff + i * PL + v;
                    float s = hadd2(acc[rr][c][i]) + outb[idx];
                    outb[idx] = s * RS_MUL + bv;
                }
        }
    }
}

#define TP_INS(n, D1, D2, D3, B1, B2, B3)                                   \
    do {                                                                    \
        float w_ = TW[(n)*128 + u];                                         \
        _Pragma("unroll") for (int xx = 0; xx < (D1); xx++)                 \
        _Pragma("unroll") for (int yy = 0; yy < (D2); yy++) {               \
            float t2 = w_ * cl[(B1) + xx] * cr[(B2) + yy];                  \
            _Pragma("unroll") for (int zz = 0; zz < (D3); zz++)             \
                o[(B3) + zz] = fmaf(t2, CF[(n)*125 + xx*25 + yy*5 + zz],    \
                                    o[(B3) + zz]);                          \
        }                                                                   \
    } while (0)

__global__ void __launch_bounds__(NT, 1)
self_layer_kernel(const float* __restrict__ x, const float* __restrict__ oldf,
                  const float* __restrict__ wl, const float* __restrict__ bl,
                  const float* __restrict__ wr, const float* __restrict__ br,
                  const float* __restrict__ wp, const float* __restrict__ bp,
                  const float* __restrict__ tpw, const float* __restrict__ lnw,
                  const float* __restrict__ lnb, float* __restrict__ out, int N) {
    extern __shared__ float sm[];
    float* A  = sm;                  /* 10*1188 */
    float* Bf = A + RPB * ROWF;
    float* Cf = Bf + RPB * ROWF;
    float* WT = Cf + RPB * ROWF;     /* 16384 : pair-major weights */
    float* CF = WT + 16384;          /* 1375 */
    float* TW = CF + 1375;           /* 1408 */
    float* RS = TW + 1408;           /* 40 */

    int t = threadIdx.x;
    int n0 = blockIdx.x * RPB;

    /* load x -> planar A */
    for (int idx = t; idx < RPB * 1152; idx += NT) {
        int r = idx / 1152, jj = idx - r * 1152;
        int n = n0 + r;
        float val = (n < N) ? x[(size_t)n * 1152 + jj] : 0.f;
        int p, u;
        if (jj < 128)      { p = 0; u = jj; }
        else if (jj < 512) { int q = jj - 128; u = q / 3; p = 1 + (q - u * 3); }
        else               { int q = jj - 512; u = q / 5; p = 4 + (q - u * 5); }
        A[r * ROWF + p * PL + u] = val;
    }
    for (int i = t; i < 1375; i += NT) CF[i] = g_coef[i];
    for (int i = t; i < 1408; i += NT) TW[i] = tpw[i];
    __syncthreads();

    int lane = t & 31, w = t >> 5;
    int rp = w % 5, ks = w / 5;

    /* lin_l : A -> Bf */
    stage_w2(wl,         WT, t); __syncthreads(); gemm2<1>(A, Bf, WT, bl, lane, rp, ks, 0);      __syncthreads();
    stage_w2(wl + 16384, WT, t); __syncthreads(); gemm2<3>(A, Bf, WT, 0,  lane, rp, ks, PL);     __syncthreads();
    stage_w2(wl + 32768, WT, t); __syncthreads(); gemm2<5>(A, Bf, WT, 0,  lane, rp, ks, 4 * PL); __syncthreads();
    /* lin_r : A -> Cf */
    stage_w2(wr,         WT, t); __syncthreads(); gemm2<1>(A, Cf, WT, br, lane, rp, ks, 0);      __syncthreads();
    stage_w2(wr + 16384, WT, t); __syncthreads(); gemm2<3>(A, Cf, WT, 0,  lane, rp, ks, PL);     __syncthreads();
    stage_w2(wr + 32768, WT, t); __syncthreads(); gemm2<5>(A, Cf, WT, 0,  lane, rp, ks, 4 * PL); __syncthreads();

    /* tensor product: Bf,Cf -> A  (10*128 = 1280 items, 4 passes exactly) */
#pragma unroll 1
    for (int it = 0; it < 4; ++it) {
        int idx = it * NT + t;
        int r = idx >> 7, u = idx & 127;
        int base = r * ROWF + u;
        float cl[9], cr[9], o[9];
#pragma unroll
        for (int c = 0; c < 9; c++) { cl[c] = Bf[base + c * PL]; cr[c] = Cf[base + c * PL]; o[c] = 0.f; }
        TP_INS(0, 1, 1, 1, 0, 0, 0);
        TP_INS(1, 1, 3, 3, 0, 1, 1);
        TP_INS(2, 1, 5, 5, 0, 4, 4);
        TP_INS(3, 3, 1, 3, 1, 0, 1);
        TP_INS(4, 3, 3, 1, 1, 1, 0);
        TP_INS(5, 3, 3, 5, 1, 1, 4);
        TP_INS(6, 3, 5, 3, 1, 4, 1);
        TP_INS(7, 5, 1, 5, 4, 0, 4);
        TP_INS(8, 5, 3, 3, 4, 1, 1);
        TP_INS(9, 5, 5, 1, 4, 4, 0);
        TP_INS(10, 5, 5, 5, 4, 4, 4);
#pragma unroll
        for (int c = 0; c < 9; c++) A[base + c * PL] = o[c];
    }
    __syncthreads();

    /* lin_p : A -> Bf */
    stage_w2(wp,         WT, t); __syncthreads(); gemm2<1>(A, Bf, WT, bp, lane, rp, ks, 0);      __syncthreads();
    stage_w2(wp + 16384, WT, t); __syncthreads(); gemm2<3>(A, Bf, WT, 0,  lane, rp, ks, PL);     __syncthreads();
    stage_w2(wp + 32768, WT, t); __syncthreads(); gemm2<5>(A, Bf, WT, 0,  lane, rp, ks, 4 * PL); __syncthreads();

    /* e3norm stats: one warp per row (10 warps, 10 rows) */
    {
        int r = w;
        const float* fr = Bf + r * ROWF;
        float s0 = 0, q0 = 0, q1 = 0, q2 = 0;
        {
            float4 a = *(const float4*)(fr + lane * 4);
            s0 = a.x + a.y + a.z + a.w;
            q0 = a.x * a.x + a.y * a.y + a.z * a.z + a.w * a.w;
        }
#pragma unroll
        for (int p = 1; p < 4; p++) {
            float4 a = *(const float4*)(fr + p * PL + lane * 4);
            q1 += a.x * a.x + a.y * a.y + a.z * a.z + a.w * a.w;
        }
#pragma unroll
        for (int p = 4; p < 9; p++) {
            float4 a = *(const float4*)(fr + p * PL + lane * 4);
            q2 += a.x * a.x + a.y * a.y + a.z * a.z + a.w * a.w;
        }
#pragma unroll
        for (int off = 16; off; off >>= 1) {
            s0 += __shfl_xor_sync(0xffffffffu, s0, off);
            q0 += __shfl_xor_sync(0xffffffffu, q0, off);
            q1 += __shfl_xor_sync(0xffffffffu, q1, off);
            q2 += __shfl_xor_sync(0xffffffffu, q2, off);
        }
        if (lane == 0) {
            float mean = s0 * (1.f / 128.f);
            RS[r * 4 + 0] = mean;
            RS[r * 4 + 1] = rsqrtf(q0 * (1.f / 128.f) - mean * mean + 1e-5f);
            RS[r * 4 + 2] = rsqrtf(q1 * (1.f / 384.f) + 1e-5f);
            RS[r * 4 + 3] = rsqrtf(q2 * (1.f / 640.f) + 1e-5f);
        }
    }
    __syncthreads();

    /* scale + bias + residual -> out */
    for (int r = 0; r < RPB; r++) {
        int n = n0 + r;
        if (n >= N) break;
        float mean = RS[r * 4], inv0 = RS[r * 4 + 1], inv1 = RS[r * 4 + 2], inv2 = RS[r * 4 + 3];
        for (int jj = t; jj < 1152; jj += NT) {
            int p, u, l;
            if (jj < 128)      { l = 0; p = 0; u = jj; }
            else if (jj < 512) { l = 1; int q = jj - 128; u = q / 3; p = 1 + (q - u * 3); }
            else               { l = 2; int q = jj - 512; u = q / 5; p = 4 + (q - u * 5); }
            float val = Bf[r * ROWF + p * PL + u];
            if (l == 0)      val = (val - mean) * inv0 * lnw[u] + lnb[u];
            else if (l == 1) val = val * inv1 * lnw[128 + u];
            else             val = val * inv2 * lnw[256 + u];
            size_t gi = (size_t)n * 1152 + jj;
            out[gi] = val + oldf[gi];
        }
    }
}

extern "C" void kernel_launch(void* const* d_in, const int* in_sizes, int n_in,
                              void* d_out, int out_size) {
    const float* x    = (const float*)d_in[0];
    const float* oldf = (const float*)d_in[1];
    const float* wl   = (const float*)d_in[2];
    const float* bl   = (const float*)d_in[3];
    const float* wr   = (const float*)d_in[4];
    const float* br   = (const float*)d_in[5];
    const float* wp   = (const float*)d_in[6];
    const float* bp   = (const float*)d_in[7];
    const float* tpw  = (const float*)d_in[8];
    const float* lnw  = (const float*)d_in[9];
    const float* lnb  = (const float*)d_in[10];
    float* out = (float*)d_out;
    int N = in_sizes[0] / 1152;

    w3j_init<<<11, 125>>>();

    size_t smem = (size_t)(3 * RPB * ROWF + 16384 + 1375 + 1408 + 40) * sizeof(float);
    cudaFuncSetAttribute(self_layer_kernel, cudaFuncAttributeMaxDynamicSharedMemorySize, (int)smem);
    int blocks = (N + RPB - 1) / RPB;
    self_layer_kernel<<<blocks, NT, smem>>>(x, oldf, wl, bl, wr, br, wp, bp, tpw, lnw, lnb, out, N);
}